// round 1
// baseline (speedup 1.0000x reference)
#include <cuda_runtime.h>
#include <cuda_bf16.h>
#include <cstdint>

// Problem constants (match reference setup_inputs)
static constexpr int NN = 50000;   // nodes
static constexpr int NE = 800000;  // edges
static constexpr int NG = 64;      // graphs
static constexpr int IN_DIM = 1056;
static constexpr int H1 = 128, H2 = 128, H3 = 64;

// ---------------- scratch (device globals, no allocation) ----------------
__device__ float g_bufA[(size_t)NN * 128];   // h (transformed features)
__device__ float g_bufB[(size_t)NN * 128];   // aggregated output
__device__ float g_deg[NN];
__device__ float g_dis[NN];      // deg^{-1/2}
__device__ float g_invdeg[NN];   // 1/deg (self-loop coefficient)
__device__ int   g_src[NE];
__device__ int   g_dst[NE];
__device__ float g_coef[NE];     // dis[src]*ew*dis[dst]
__device__ int   g_batch[NN];
__device__ float g_gsum[NG * H3];
__device__ float g_gcnt[NG];
__device__ int   g_is64;

// ---------------- dtype detection for edge_index / batch -----------------
// If the indices are int64, every odd 32-bit word (high half) is 0 (values < 50000).
// If int32, odd words are random indices -> OR is nonzero with overwhelming prob.
__global__ void detect_kernel(const unsigned int* __restrict__ p) {
    __shared__ unsigned int sh[256];
    unsigned int acc = 0;
    for (int i = threadIdx.x; i < 1024; i += 256) acc |= p[2 * i + 1];
    sh[threadIdx.x] = acc;
    __syncthreads();
    for (int s = 128; s > 0; s >>= 1) {
        if (threadIdx.x < s) sh[threadIdx.x] |= sh[threadIdx.x + s];
        __syncthreads();
    }
    if (threadIdx.x == 0) g_is64 = (sh[0] == 0u) ? 1 : 0;
}

__global__ void convert_edges_kernel(const void* __restrict__ ei) {
    int i = blockIdx.x * blockDim.x + threadIdx.x;
    if (i >= NE) return;
    if (g_is64) {
        const long long* p = (const long long*)ei;
        g_src[i] = (int)p[i];
        g_dst[i] = (int)p[NE + i];
    } else {
        const int* p = (const int*)ei;
        g_src[i] = p[i];
        g_dst[i] = p[NE + i];
    }
}

__global__ void convert_batch_kernel(const void* __restrict__ b) {
    int i = blockIdx.x * blockDim.x + threadIdx.x;
    if (i >= NN) return;
    if (g_is64) {
        const long long* p = (const long long*)b;
        g_batch[i] = (int)p[i];
    } else {
        const int* p = (const int*)b;
        g_batch[i] = p[i];
    }
}

// ---------------- degree / normalization ----------------
__global__ void init_deg_kernel() {
    int i = blockIdx.x * blockDim.x + threadIdx.x;
    if (i < NN) g_deg[i] = 1.0f;  // self-loop weight 1
}

__global__ void accum_deg_kernel(const float* __restrict__ ew) {
    int e = blockIdx.x * blockDim.x + threadIdx.x;
    if (e < NE) atomicAdd(&g_deg[g_dst[e]], ew[e]);
}

__global__ void dis_kernel() {
    int i = blockIdx.x * blockDim.x + threadIdx.x;
    if (i < NN) {
        float d = g_deg[i];          // >= 1 always (self-loop)
        g_dis[i] = rsqrtf(d);
        g_invdeg[i] = 1.0f / d;
    }
}

__global__ void coef_kernel(const float* __restrict__ ew) {
    int e = blockIdx.x * blockDim.x + threadIdx.x;
    if (e < NE) {
        int s = g_src[e], d = g_dst[e];
        g_coef[e] = g_dis[s] * ew[e] * g_dis[d];
    }
}

// ---------------- SGEMM: C[M,N] = act(A)[M,K] @ B[K,N] ----------------
// ACT==1: a <- relu(a + bias[k])  (bias/relu of the previous GCN layer fused
// into the A-tile load of the next layer's transform)
template <int BM, int BN, int BK, int TM, int TN, int ACT>
__global__ void sgemm_kernel(int M, int K, int N,
                             const float* __restrict__ A,
                             const float* __restrict__ B,
                             float* __restrict__ C,
                             const float* __restrict__ bias) {
    __shared__ float As[BK][BM];
    __shared__ float Bs[BK][BN];
    constexpr int NT = (BM / TM) * (BN / TN);
    const int tid = threadIdx.x;
    const int tcol = tid % (BN / TN);
    const int trow = tid / (BN / TN);
    const int rowBase = blockIdx.y * BM;
    const int colBase = blockIdx.x * BN;

    float acc[TM][TN] = {};
    float regM[TM], regN[TN];

    for (int k0 = 0; k0 < K; k0 += BK) {
        // A tile: BM x BK, float4 along K, stored transposed
        #pragma unroll
        for (int idx = tid; idx < BM * BK / 4; idx += NT) {
            int r = idx / (BK / 4);
            int c = (idx % (BK / 4)) * 4;
            int gr = rowBase + r;
            float4 v;
            if (gr < M) {
                v = *(const float4*)(A + (size_t)gr * K + k0 + c);
                if (ACT) {
                    v.x = fmaxf(v.x + bias[k0 + c + 0], 0.0f);
                    v.y = fmaxf(v.y + bias[k0 + c + 1], 0.0f);
                    v.z = fmaxf(v.z + bias[k0 + c + 2], 0.0f);
                    v.w = fmaxf(v.w + bias[k0 + c + 3], 0.0f);
                }
            } else {
                v = make_float4(0.f, 0.f, 0.f, 0.f);
            }
            As[c + 0][r] = v.x;
            As[c + 1][r] = v.y;
            As[c + 2][r] = v.z;
            As[c + 3][r] = v.w;
        }
        // B tile: BK x BN (N is always a multiple of BN in this problem)
        #pragma unroll
        for (int idx = tid; idx < BK * BN / 4; idx += NT) {
            int r = idx / (BN / 4);
            int c = (idx % (BN / 4)) * 4;
            *(float4*)&Bs[r][c] = *(const float4*)(B + (size_t)(k0 + r) * N + colBase + c);
        }
        __syncthreads();

        #pragma unroll
        for (int kk = 0; kk < BK; kk++) {
            #pragma unroll
            for (int i = 0; i < TM; i++) regM[i] = As[kk][trow * TM + i];
            #pragma unroll
            for (int j = 0; j < TN; j++) regN[j] = Bs[kk][tcol * TN + j];
            #pragma unroll
            for (int i = 0; i < TM; i++)
                #pragma unroll
                for (int j = 0; j < TN; j++) acc[i][j] += regM[i] * regN[j];
        }
        __syncthreads();
    }

    #pragma unroll
    for (int i = 0; i < TM; i++) {
        int gr = rowBase + trow * TM + i;
        if (gr < M) {
            #pragma unroll
            for (int j = 0; j < TN; j += 4) {
                float4 v = make_float4(acc[i][j], acc[i][j + 1], acc[i][j + 2], acc[i][j + 3]);
                *(float4*)(C + (size_t)gr * N + colBase + tcol * TN + j) = v;
            }
        }
    }
}

// ---------------- self-loop init: out = h * (1/deg) ----------------
template <int DIM>
__global__ void selfloop_kernel(const float* __restrict__ h, float* __restrict__ out) {
    int idx = blockIdx.x * blockDim.x + threadIdx.x;
    if (idx >= NN * DIM) return;
    int n = idx / DIM;
    out[idx] = h[idx] * g_invdeg[n];
}

// ---------------- edge scatter: out[dst] += coef * h[src] ----------------
__global__ void scatter128_kernel(const float* __restrict__ h, float* __restrict__ out) {
    long long t = (long long)blockIdx.x * blockDim.x + threadIdx.x;
    int e = (int)(t >> 5);
    if (e >= NE) return;
    int lane = (int)(t & 31);
    int s = g_src[e], d = g_dst[e];
    float c = g_coef[e];
    float4 v = *(const float4*)(h + (size_t)s * 128 + lane * 4);
    float* o = out + (size_t)d * 128 + lane * 4;
    atomicAdd(o + 0, v.x * c);
    atomicAdd(o + 1, v.y * c);
    atomicAdd(o + 2, v.z * c);
    atomicAdd(o + 3, v.w * c);
}

__global__ void scatter64_kernel(const float* __restrict__ h, float* __restrict__ out) {
    long long t = (long long)blockIdx.x * blockDim.x + threadIdx.x;
    int e = (int)(t >> 4);
    if (e >= NE) return;
    int lane = (int)(t & 15);
    int s = g_src[e], d = g_dst[e];
    float c = g_coef[e];
    float4 v = *(const float4*)(h + (size_t)s * 64 + lane * 4);
    float* o = out + (size_t)d * 64 + lane * 4;
    atomicAdd(o + 0, v.x * c);
    atomicAdd(o + 1, v.y * c);
    atomicAdd(o + 2, v.z * c);
    atomicAdd(o + 3, v.w * c);
}

// ---------------- pooling + head ----------------
__global__ void zero_pool_kernel() {
    int i = blockIdx.x * blockDim.x + threadIdx.x;
    if (i < NG * H3) g_gsum[i] = 0.0f;
    else if (i < NG * H3 + NG) g_gcnt[i - NG * H3] = 0.0f;
}

__global__ void pool_kernel(const float* __restrict__ agg3) {
    int idx = blockIdx.x * blockDim.x + threadIdx.x;
    if (idx >= NN * H3) return;
    int n = idx >> 6;
    int c = idx & 63;
    int g = g_batch[n];
    atomicAdd(&g_gsum[g * H3 + c], agg3[idx]);
    if (c == 0) atomicAdd(&g_gcnt[g], 1.0f);
}

__global__ void final_kernel(const float* __restrict__ Wlin,
                             const float* __restrict__ blin,
                             const float* __restrict__ b3,
                             float* __restrict__ out) {
    int g = threadIdx.x;
    if (g >= NG) return;
    float inv = 1.0f / fmaxf(g_gcnt[g], 1.0f);
    float a0 = blin[0], a1 = blin[1], a2 = blin[2];
    #pragma unroll 8
    for (int c = 0; c < H3; c++) {
        float p = g_gsum[g * H3 + c] * inv + b3[c];  // mean(agg)+b3 == mean(agg+b3)
        a0 += p * Wlin[c * 3 + 0];
        a1 += p * Wlin[c * 3 + 1];
        a2 += p * Wlin[c * 3 + 2];
    }
    out[g * 3 + 0] = a0;
    out[g * 3 + 1] = a1;
    out[g * 3 + 2] = a2;
}

// ---------------- launch ----------------
extern "C" void kernel_launch(void* const* d_in, const int* in_sizes, int n_in,
                              void* d_out, int out_size) {
    const float* x    = (const float*)d_in[0];
    const void*  ei   = d_in[1];
    const float* ew   = (const float*)d_in[2];
    const void*  bat  = d_in[3];
    const float* W1   = (const float*)d_in[4];
    const float* b1   = (const float*)d_in[5];
    const float* W2   = (const float*)d_in[6];
    const float* b2   = (const float*)d_in[7];
    const float* W3   = (const float*)d_in[8];
    const float* b3   = (const float*)d_in[9];
    const float* Wlin = (const float*)d_in[10];
    const float* blin = (const float*)d_in[11];
    float* out = (float*)d_out;

    float *bufA, *bufB;
    cudaGetSymbolAddress((void**)&bufA, g_bufA);
    cudaGetSymbolAddress((void**)&bufB, g_bufB);

    const int TPB = 256;
    const int gE = (NE + TPB - 1) / TPB;
    const int gN = (NN + TPB - 1) / TPB;

    // index dtype detection + conversion
    detect_kernel<<<1, 256>>>((const unsigned int*)ei);
    convert_edges_kernel<<<gE, TPB>>>(ei);
    convert_batch_kernel<<<gN, TPB>>>(bat);

    // normalization
    init_deg_kernel<<<gN, TPB>>>();
    accum_deg_kernel<<<gE, TPB>>>(ew);
    dis_kernel<<<gN, TPB>>>();
    coef_kernel<<<gE, TPB>>>(ew);

    const int MB = (NN + 127) / 128;  // 391 row-blocks
    dim3 g128(1, MB), g64(1, MB);

    // ---- layer 1: h1 = x @ W1 ; agg1 = Ahat h1 ----
    sgemm_kernel<128, 128, 8, 8, 8, 0><<<g128, 256>>>(NN, IN_DIM, H1, x, W1, bufA, nullptr);
    selfloop_kernel<128><<<(NN * 128 + TPB - 1) / TPB, TPB>>>(bufA, bufB);
    scatter128_kernel<<<(NE * 32 + TPB - 1) / TPB, TPB>>>(bufA, bufB);

    // ---- layer 2: h2 = relu(agg1 + b1) @ W2 ; agg2 = Ahat h2 ----
    sgemm_kernel<128, 128, 8, 8, 8, 1><<<g128, 256>>>(NN, H1, H2, bufB, W2, bufA, b1);
    selfloop_kernel<128><<<(NN * 128 + TPB - 1) / TPB, TPB>>>(bufA, bufB);
    scatter128_kernel<<<(NE * 32 + TPB - 1) / TPB, TPB>>>(bufA, bufB);

    // ---- layer 3: h3 = relu(agg2 + b2) @ W3 ; agg3 = Ahat h3 ----
    sgemm_kernel<128, 64, 8, 8, 4, 1><<<g64, 256>>>(NN, H2, H3, bufB, W3, bufA, b2);
    selfloop_kernel<64><<<(NN * 64 + TPB - 1) / TPB, TPB>>>(bufA, bufB);
    scatter64_kernel<<<(NE * 16 + TPB - 1) / TPB, TPB>>>(bufA, bufB);

    // ---- pool + head ----
    zero_pool_kernel<<<(NG * H3 + NG + TPB - 1) / TPB, TPB>>>();
    pool_kernel<<<(NN * H3 + TPB - 1) / TPB, TPB>>>(bufB);
    final_kernel<<<1, 64>>>(Wlin, blin, b3, out);
}

// round 2
// speedup vs baseline: 1.6400x; 1.6400x over previous
#include <cuda_runtime.h>
#include <cuda_bf16.h>
#include <cstdint>

// Problem constants (match reference setup_inputs)
static constexpr int NN = 50000;   // nodes
static constexpr int NE = 800000;  // edges
static constexpr int NG = 64;      // graphs
static constexpr int IN_DIM = 1056;
static constexpr int H1 = 128, H2 = 128, H3 = 64;

// ---------------- scratch (device globals, no allocation) ----------------
__device__ float g_bufA[(size_t)NN * 128];   // h (transformed features)
__device__ float g_bufB[(size_t)NN * 128];   // aggregated output
__device__ float g_deg[NN];
__device__ float g_dis[NN];      // deg^{-1/2}
__device__ float g_invdeg[NN];   // 1/deg (self-loop coefficient)
__device__ int   g_src[NE];
__device__ int   g_dst[NE];
__device__ int   g_batch[NN];
__device__ float g_gsum[NG * H3];
__device__ float g_gcnt[NG];
__device__ int   g_is64;

// CSR structures (by destination node)
__device__ int   g_cnt[NN];      // in-degree (edge count)
__device__ int   g_start[NN];    // exclusive prefix (CSR row start)
__device__ int   g_cur[NN];      // fill cursor
__device__ int   g_part[256];    // block partial sums for scan
__device__ int   g_csr_src[NE];
__device__ float g_csr_coef[NE];

// ---------------- dtype detection for edge_index / batch -----------------
__global__ void detect_kernel(const unsigned int* __restrict__ p) {
    __shared__ unsigned int sh[256];
    unsigned int acc = 0;
    for (int i = threadIdx.x; i < 1024; i += 256) acc |= p[2 * i + 1];
    sh[threadIdx.x] = acc;
    __syncthreads();
    for (int s = 128; s > 0; s >>= 1) {
        if (threadIdx.x < s) sh[threadIdx.x] |= sh[threadIdx.x + s];
        __syncthreads();
    }
    if (threadIdx.x == 0) g_is64 = (sh[0] == 0u) ? 1 : 0;
}

__global__ void convert_edges_kernel(const void* __restrict__ ei) {
    int i = blockIdx.x * blockDim.x + threadIdx.x;
    if (i >= NE) return;
    if (g_is64) {
        const long long* p = (const long long*)ei;
        g_src[i] = (int)p[i];
        g_dst[i] = (int)p[NE + i];
    } else {
        const int* p = (const int*)ei;
        g_src[i] = p[i];
        g_dst[i] = p[NE + i];
    }
}

__global__ void convert_batch_kernel(const void* __restrict__ b) {
    int i = blockIdx.x * blockDim.x + threadIdx.x;
    if (i >= NN) return;
    if (g_is64) {
        const long long* p = (const long long*)b;
        g_batch[i] = (int)p[i];
    } else {
        const int* p = (const int*)b;
        g_batch[i] = p[i];
    }
}

// ---------------- degree / counts init ----------------
__global__ void init_node_kernel() {
    int i = blockIdx.x * blockDim.x + threadIdx.x;
    if (i < NN) {
        g_deg[i] = 1.0f;  // self-loop weight 1
        g_cnt[i] = 0;
        g_cur[i] = 0;
    }
}

// per-edge: accumulate weighted degree and in-edge count at dst
__global__ void accum_deg_kernel(const float* __restrict__ ew) {
    int e = blockIdx.x * blockDim.x + threadIdx.x;
    if (e < NE) {
        int d = g_dst[e];
        atomicAdd(&g_deg[d], ew[e]);
        atomicAdd(&g_cnt[d], 1);
    }
}

__global__ void dis_kernel() {
    int i = blockIdx.x * blockDim.x + threadIdx.x;
    if (i < NN) {
        float d = g_deg[i];  // >= 1 always (self-loop)
        g_dis[i] = rsqrtf(d);
        g_invdeg[i] = 1.0f / d;
    }
}

// ---------------- exclusive scan of g_cnt -> g_start (3 kernels) ---------
__global__ void scan1_kernel() {
    __shared__ int sh[256];
    int i = blockIdx.x * 256 + threadIdx.x;
    int v = (i < NN) ? g_cnt[i] : 0;
    sh[threadIdx.x] = v;
    __syncthreads();
    #pragma unroll
    for (int off = 1; off < 256; off <<= 1) {
        int t = (threadIdx.x >= off) ? sh[threadIdx.x - off] : 0;
        __syncthreads();
        sh[threadIdx.x] += t;
        __syncthreads();
    }
    if (i < NN) g_start[i] = sh[threadIdx.x] - v;  // exclusive within chunk
    if (threadIdx.x == 255) g_part[blockIdx.x] = sh[255];
}

__global__ void scan2_kernel(int nblocks) {
    __shared__ int sh[256];
    int v = (threadIdx.x < nblocks) ? g_part[threadIdx.x] : 0;
    sh[threadIdx.x] = v;
    __syncthreads();
    #pragma unroll
    for (int off = 1; off < 256; off <<= 1) {
        int t = (threadIdx.x >= off) ? sh[threadIdx.x - off] : 0;
        __syncthreads();
        sh[threadIdx.x] += t;
        __syncthreads();
    }
    g_part[threadIdx.x] = sh[threadIdx.x] - v;  // exclusive over blocks
}

__global__ void scan3_kernel() {
    int i = blockIdx.x * 256 + threadIdx.x;
    if (i < NN) g_start[i] += g_part[i >> 8];
}

// ---------------- CSR fill with normalized coefficients ----------------
__global__ void fill_kernel(const float* __restrict__ ew) {
    int e = blockIdx.x * blockDim.x + threadIdx.x;
    if (e >= NE) return;
    int s = g_src[e], d = g_dst[e];
    int p = g_start[d] + atomicAdd(&g_cur[d], 1);
    g_csr_src[p] = s;
    g_csr_coef[p] = g_dis[s] * ew[e] * g_dis[d];
}

// ---------------- SGEMM: C[M,N] = act(A)[M,K] @ B[K,N] ----------------
// ACT==1: a <- relu(a + bias[k])
template <int BM, int BN, int BK, int TM, int TN, int ACT>
__global__ void sgemm_kernel(int M, int K, int N,
                             const float* __restrict__ A,
                             const float* __restrict__ B,
                             float* __restrict__ C,
                             const float* __restrict__ bias) {
    __shared__ float As[BK][BM];
    __shared__ float Bs[BK][BN];
    constexpr int NT = (BM / TM) * (BN / TN);
    const int tid = threadIdx.x;
    const int tcol = tid % (BN / TN);
    const int trow = tid / (BN / TN);
    const int rowBase = blockIdx.y * BM;
    const int colBase = blockIdx.x * BN;

    float acc[TM][TN] = {};
    float regM[TM], regN[TN];

    for (int k0 = 0; k0 < K; k0 += BK) {
        #pragma unroll
        for (int idx = tid; idx < BM * BK / 4; idx += NT) {
            int r = idx / (BK / 4);
            int c = (idx % (BK / 4)) * 4;
            int gr = rowBase + r;
            float4 v;
            if (gr < M) {
                v = *(const float4*)(A + (size_t)gr * K + k0 + c);
                if (ACT) {
                    v.x = fmaxf(v.x + bias[k0 + c + 0], 0.0f);
                    v.y = fmaxf(v.y + bias[k0 + c + 1], 0.0f);
                    v.z = fmaxf(v.z + bias[k0 + c + 2], 0.0f);
                    v.w = fmaxf(v.w + bias[k0 + c + 3], 0.0f);
                }
            } else {
                v = make_float4(0.f, 0.f, 0.f, 0.f);
            }
            As[c + 0][r] = v.x;
            As[c + 1][r] = v.y;
            As[c + 2][r] = v.z;
            As[c + 3][r] = v.w;
        }
        #pragma unroll
        for (int idx = tid; idx < BK * BN / 4; idx += NT) {
            int r = idx / (BN / 4);
            int c = (idx % (BN / 4)) * 4;
            *(float4*)&Bs[r][c] = *(const float4*)(B + (size_t)(k0 + r) * N + colBase + c);
        }
        __syncthreads();

        #pragma unroll
        for (int kk = 0; kk < BK; kk++) {
            #pragma unroll
            for (int i = 0; i < TM; i++) regM[i] = As[kk][trow * TM + i];
            #pragma unroll
            for (int j = 0; j < TN; j++) regN[j] = Bs[kk][tcol * TN + j];
            #pragma unroll
            for (int i = 0; i < TM; i++)
                #pragma unroll
                for (int j = 0; j < TN; j++) acc[i][j] += regM[i] * regN[j];
        }
        __syncthreads();
    }

    #pragma unroll
    for (int i = 0; i < TM; i++) {
        int gr = rowBase + trow * TM + i;
        if (gr < M) {
            #pragma unroll
            for (int j = 0; j < TN; j += 4) {
                float4 v = make_float4(acc[i][j], acc[i][j + 1], acc[i][j + 2], acc[i][j + 3]);
                *(float4*)(C + (size_t)gr * N + colBase + tcol * TN + j) = v;
            }
        }
    }
}

// ---------------- CSR aggregation (warp per node, selfloop fused) --------
// out[n] = h[n]/deg[n] + sum_{incoming e} coef[e] * h[src[e]]
__global__ void agg128_kernel(const float* __restrict__ h, float* __restrict__ out) {
    int n = blockIdx.x * 8 + (threadIdx.x >> 5);
    if (n >= NN) return;
    int lane = threadIdx.x & 31;

    float4 acc = *(const float4*)(h + (size_t)n * 128 + lane * 4);
    float w = g_invdeg[n];
    acc.x *= w; acc.y *= w; acc.z *= w; acc.w *= w;

    int beg = g_start[n];
    int end = beg + g_cnt[n];
    for (int j = beg; j < end; j++) {
        int s = g_csr_src[j];            // warp-uniform broadcast load
        float c = g_csr_coef[j];
        float4 v = *(const float4*)(h + (size_t)s * 128 + lane * 4);
        acc.x = fmaf(c, v.x, acc.x);
        acc.y = fmaf(c, v.y, acc.y);
        acc.z = fmaf(c, v.z, acc.z);
        acc.w = fmaf(c, v.w, acc.w);
    }
    *(float4*)(out + (size_t)n * 128 + lane * 4) = acc;
}

__global__ void agg64_kernel(const float* __restrict__ h, float* __restrict__ out) {
    int n = blockIdx.x * 8 + (threadIdx.x >> 5);
    if (n >= NN) return;
    int lane = threadIdx.x & 31;

    float2 acc = *(const float2*)(h + (size_t)n * 64 + lane * 2);
    float w = g_invdeg[n];
    acc.x *= w; acc.y *= w;

    int beg = g_start[n];
    int end = beg + g_cnt[n];
    for (int j = beg; j < end; j++) {
        int s = g_csr_src[j];
        float c = g_csr_coef[j];
        float2 v = *(const float2*)(h + (size_t)s * 64 + lane * 2);
        acc.x = fmaf(c, v.x, acc.x);
        acc.y = fmaf(c, v.y, acc.y);
    }
    *(float2*)(out + (size_t)n * 64 + lane * 2) = acc;
}

// ---------------- pooling + head ----------------
__global__ void zero_pool_kernel() {
    int i = blockIdx.x * blockDim.x + threadIdx.x;
    if (i < NG * H3) g_gsum[i] = 0.0f;
    else if (i < NG * H3 + NG) g_gcnt[i - NG * H3] = 0.0f;
}

__global__ void pool_kernel(const float* __restrict__ agg3) {
    int idx = blockIdx.x * blockDim.x + threadIdx.x;
    if (idx >= NN * H3) return;
    int n = idx >> 6;
    int c = idx & 63;
    int g = g_batch[n];
    atomicAdd(&g_gsum[g * H3 + c], agg3[idx]);
    if (c == 0) atomicAdd(&g_gcnt[g], 1.0f);
}

__global__ void final_kernel(const float* __restrict__ Wlin,
                             const float* __restrict__ blin,
                             const float* __restrict__ b3,
                             float* __restrict__ out) {
    int g = threadIdx.x;
    if (g >= NG) return;
    float inv = 1.0f / fmaxf(g_gcnt[g], 1.0f);
    float a0 = blin[0], a1 = blin[1], a2 = blin[2];
    #pragma unroll 8
    for (int c = 0; c < H3; c++) {
        float p = g_gsum[g * H3 + c] * inv + b3[c];  // mean(agg)+b3 == mean(agg+b3)
        a0 += p * Wlin[c * 3 + 0];
        a1 += p * Wlin[c * 3 + 1];
        a2 += p * Wlin[c * 3 + 2];
    }
    out[g * 3 + 0] = a0;
    out[g * 3 + 1] = a1;
    out[g * 3 + 2] = a2;
}

// ---------------- launch ----------------
extern "C" void kernel_launch(void* const* d_in, const int* in_sizes, int n_in,
                              void* d_out, int out_size) {
    const float* x    = (const float*)d_in[0];
    const void*  ei   = d_in[1];
    const float* ew   = (const float*)d_in[2];
    const void*  bat  = d_in[3];
    const float* W1   = (const float*)d_in[4];
    const float* b1   = (const float*)d_in[5];
    const float* W2   = (const float*)d_in[6];
    const float* b2   = (const float*)d_in[7];
    const float* W3   = (const float*)d_in[8];
    const float* b3   = (const float*)d_in[9];
    const float* Wlin = (const float*)d_in[10];
    const float* blin = (const float*)d_in[11];
    float* out = (float*)d_out;

    float *bufA, *bufB;
    cudaGetSymbolAddress((void**)&bufA, g_bufA);
    cudaGetSymbolAddress((void**)&bufB, g_bufB);

    const int TPB = 256;
    const int gE = (NE + TPB - 1) / TPB;
    const int gN = (NN + TPB - 1) / TPB;
    const int nChunks = (NN + 255) / 256;  // 196

    // index dtype detection + conversion
    detect_kernel<<<1, 256>>>((const unsigned int*)ei);
    convert_edges_kernel<<<gE, TPB>>>(ei);
    convert_batch_kernel<<<gN, TPB>>>(bat);

    // degree + CSR build
    init_node_kernel<<<gN, TPB>>>();
    accum_deg_kernel<<<gE, TPB>>>(ew);
    dis_kernel<<<gN, TPB>>>();
    scan1_kernel<<<nChunks, 256>>>();
    scan2_kernel<<<1, 256>>>(nChunks);
    scan3_kernel<<<nChunks, 256>>>();
    fill_kernel<<<gE, TPB>>>(ew);

    const int MB = (NN + 127) / 128;  // 391 row-blocks
    dim3 g128(1, MB), g64(1, MB);
    const int gAgg = (NN + 7) / 8;    // warp per node, 8 warps/block

    // ---- layer 1: h1 = x @ W1 ; agg1 = Ahat h1 ----
    sgemm_kernel<128, 128, 8, 8, 8, 0><<<g128, 256>>>(NN, IN_DIM, H1, x, W1, bufA, nullptr);
    agg128_kernel<<<gAgg, 256>>>(bufA, bufB);

    // ---- layer 2: h2 = relu(agg1 + b1) @ W2 ; agg2 = Ahat h2 ----
    sgemm_kernel<128, 128, 8, 8, 8, 1><<<g128, 256>>>(NN, H1, H2, bufB, W2, bufA, b1);
    agg128_kernel<<<gAgg, 256>>>(bufA, bufB);

    // ---- layer 3: h3 = relu(agg2 + b2) @ W3 ; agg3 = Ahat h3 ----
    sgemm_kernel<128, 64, 8, 8, 4, 1><<<g64, 256>>>(NN, H2, H3, bufB, W3, bufA, b2);
    agg64_kernel<<<gAgg, 256>>>(bufA, bufB);

    // ---- pool + head ----
    zero_pool_kernel<<<(NG * H3 + NG + TPB - 1) / TPB, TPB>>>();
    pool_kernel<<<(NN * H3 + TPB - 1) / TPB, TPB>>>(bufB);
    final_kernel<<<1, 64>>>(Wlin, blin, b3, out);
}

// round 3
// speedup vs baseline: 3.0159x; 1.8389x over previous
#include <cuda_runtime.h>
#include <cuda_bf16.h>
#include <cstdint>

// Problem constants (match reference setup_inputs)
static constexpr int NN = 50000;   // nodes
static constexpr int NE = 800000;  // edges
static constexpr int NG = 64;      // graphs
static constexpr int IN_DIM = 1056;
static constexpr int H1 = 128, H2 = 128, H3 = 64;

// ---------------- scratch (device globals, no allocation) ----------------
__device__ float g_bufA[(size_t)NN * 128];   // h (transformed features)
__device__ float g_bufB[(size_t)NN * 128];   // aggregated output
__device__ float g_deg[NN];
__device__ float g_dis[NN];      // deg^{-1/2}
__device__ float g_invdeg[NN];   // 1/deg (self-loop coefficient)
__device__ int   g_src[NE];
__device__ int   g_dst[NE];
__device__ int   g_batch[NN];
__device__ float g_gsum[NG * H3];
__device__ float g_gcnt[NG];
__device__ int   g_is64;

// CSR structures (by destination node)
__device__ int   g_cnt[NN];
__device__ int   g_start[NN];
__device__ int   g_cur[NN];
__device__ int   g_part[256];
__device__ int   g_csr_src[NE];
__device__ float g_csr_coef[NE];

// split-bf16 transposed weights: [N][K] row-major (k contiguous)
__device__ __nv_bfloat16 g_w1t_hi[H1 * IN_DIM], g_w1t_lo[H1 * IN_DIM];
__device__ __nv_bfloat16 g_w2t_hi[H2 * H1],     g_w2t_lo[H2 * H1];
__device__ __nv_bfloat16 g_w3t_hi[H3 * H2],     g_w3t_lo[H3 * H2];

// ---------------- dtype detection for edge_index / batch -----------------
__global__ void detect_kernel(const unsigned int* __restrict__ p) {
    __shared__ unsigned int sh[256];
    unsigned int acc = 0;
    for (int i = threadIdx.x; i < 1024; i += 256) acc |= p[2 * i + 1];
    sh[threadIdx.x] = acc;
    __syncthreads();
    for (int s = 128; s > 0; s >>= 1) {
        if (threadIdx.x < s) sh[threadIdx.x] |= sh[threadIdx.x + s];
        __syncthreads();
    }
    if (threadIdx.x == 0) g_is64 = (sh[0] == 0u) ? 1 : 0;
}

__global__ void convert_edges_kernel(const void* __restrict__ ei) {
    int i = blockIdx.x * blockDim.x + threadIdx.x;
    if (i >= NE) return;
    if (g_is64) {
        const long long* p = (const long long*)ei;
        g_src[i] = (int)p[i];
        g_dst[i] = (int)p[NE + i];
    } else {
        const int* p = (const int*)ei;
        g_src[i] = p[i];
        g_dst[i] = p[NE + i];
    }
}

__global__ void convert_batch_kernel(const void* __restrict__ b) {
    int i = blockIdx.x * blockDim.x + threadIdx.x;
    if (i >= NN) return;
    if (g_is64) {
        const long long* p = (const long long*)b;
        g_batch[i] = (int)p[i];
    } else {
        const int* p = (const int*)b;
        g_batch[i] = p[i];
    }
}

// ---------------- degree / counts init ----------------
__global__ void init_node_kernel() {
    int i = blockIdx.x * blockDim.x + threadIdx.x;
    if (i < NN) {
        g_deg[i] = 1.0f;
        g_cnt[i] = 0;
        g_cur[i] = 0;
    }
}

__global__ void accum_deg_kernel(const float* __restrict__ ew) {
    int e = blockIdx.x * blockDim.x + threadIdx.x;
    if (e < NE) {
        int d = g_dst[e];
        atomicAdd(&g_deg[d], ew[e]);
        atomicAdd(&g_cnt[d], 1);
    }
}

__global__ void dis_kernel() {
    int i = blockIdx.x * blockDim.x + threadIdx.x;
    if (i < NN) {
        float d = g_deg[i];
        g_dis[i] = rsqrtf(d);
        g_invdeg[i] = 1.0f / d;
    }
}

// ---------------- exclusive scan of g_cnt -> g_start ----------------
__global__ void scan1_kernel() {
    __shared__ int sh[256];
    int i = blockIdx.x * 256 + threadIdx.x;
    int v = (i < NN) ? g_cnt[i] : 0;
    sh[threadIdx.x] = v;
    __syncthreads();
    #pragma unroll
    for (int off = 1; off < 256; off <<= 1) {
        int t = (threadIdx.x >= off) ? sh[threadIdx.x - off] : 0;
        __syncthreads();
        sh[threadIdx.x] += t;
        __syncthreads();
    }
    if (i < NN) g_start[i] = sh[threadIdx.x] - v;
    if (threadIdx.x == 255) g_part[blockIdx.x] = sh[255];
}

__global__ void scan2_kernel(int nblocks) {
    __shared__ int sh[256];
    int v = (threadIdx.x < nblocks) ? g_part[threadIdx.x] : 0;
    sh[threadIdx.x] = v;
    __syncthreads();
    #pragma unroll
    for (int off = 1; off < 256; off <<= 1) {
        int t = (threadIdx.x >= off) ? sh[threadIdx.x - off] : 0;
        __syncthreads();
        sh[threadIdx.x] += t;
        __syncthreads();
    }
    g_part[threadIdx.x] = sh[threadIdx.x] - v;
}

__global__ void scan3_kernel() {
    int i = blockIdx.x * 256 + threadIdx.x;
    if (i < NN) g_start[i] += g_part[i >> 8];
}

__global__ void fill_kernel(const float* __restrict__ ew) {
    int e = blockIdx.x * blockDim.x + threadIdx.x;
    if (e >= NE) return;
    int s = g_src[e], d = g_dst[e];
    int p = g_start[d] + atomicAdd(&g_cur[d], 1);
    g_csr_src[p] = s;
    g_csr_coef[p] = g_dis[s] * ew[e] * g_dis[d];
}

// ---------------- weight transpose + bf16 hi/lo split ----------------
// W[K][N] (row-major) -> hi/lo [N][K]
__global__ void wsplit_kernel(const float* __restrict__ W,
                              __nv_bfloat16* __restrict__ hi,
                              __nv_bfloat16* __restrict__ lo,
                              int K, int N) {
    int idx = blockIdx.x * blockDim.x + threadIdx.x;
    if (idx >= K * N) return;
    int n = idx / K, k = idx % K;
    float v = W[(size_t)k * N + n];
    __nv_bfloat16 h = __float2bfloat16(v);
    hi[idx] = h;
    lo[idx] = __float2bfloat16(v - __bfloat162float(h));
}

// ---------------- tensor-core GEMM: C[M,N] = act(A)[M,K] @ B[K,N] --------
// A fp32 (optionally relu(a+bias)); B pre-split as Bt_hi/lo[N][K].
// Split-bf16: acc += Ahi*Bhi + Ahi*Blo + Alo*Bhi (fp32 accum via mma.sync).
#define MMA_BF16(d, a, b0, b1)                                              \
    asm volatile(                                                           \
        "mma.sync.aligned.m16n8k16.row.col.f32.bf16.bf16.f32 "              \
        "{%0,%1,%2,%3}, {%4,%5,%6,%7}, {%8,%9}, {%0,%1,%2,%3};"             \
        : "+f"(d[0]), "+f"(d[1]), "+f"(d[2]), "+f"(d[3])                    \
        : "r"(a[0]), "r"(a[1]), "r"(a[2]), "r"(a[3]), "r"(b0), "r"(b1))

template <int BN, int ACT>  // BM=128, BK=32; BN == N (<=128)
__global__ __launch_bounds__(256) void hgemm_kernel(
    int M, int K,
    const float* __restrict__ A,
    const __nv_bfloat16* __restrict__ Bt_hi,
    const __nv_bfloat16* __restrict__ Bt_lo,
    float* __restrict__ C,
    const float* __restrict__ bias) {

    constexpr int SK = 40;           // smem k-stride (bf16), conflict-free
    constexpr int NT = BN / 2 / 8;   // n-tiles per warp (8 or 4)
    constexpr int BI = BN * 4 / 256; // B uint4 items per thread (2 or 1)

    __shared__ __align__(16) __nv_bfloat16 As_hi[128][SK];
    __shared__ __align__(16) __nv_bfloat16 As_lo[128][SK];
    __shared__ __align__(16) __nv_bfloat16 Bs_hi[BN][SK];
    __shared__ __align__(16) __nv_bfloat16 Bs_lo[BN][SK];

    const int tid = threadIdx.x;
    const int wid = tid >> 5, lane = tid & 31;
    const int wm = wid >> 1;            // 0..3
    const int wn = wid & 1;             // 0..1
    const int mBase = wm * 32;
    const int nBase = wn * (BN / 2);
    const int g = lane >> 2, t = lane & 3;
    const int rowBase = blockIdx.y * 128;

    float acc[2][NT][4];
    #pragma unroll
    for (int i = 0; i < 2; i++)
        #pragma unroll
        for (int j = 0; j < NT; j++)
            #pragma unroll
            for (int r = 0; r < 4; r++) acc[i][j][r] = 0.0f;

    float4 aReg[4];
    uint4 bRegH[BI], bRegL[BI];

    auto loadTile = [&](int k0) {
        #pragma unroll
        for (int i = 0; i < 4; i++) {
            int it = tid + i * 256;
            int r = it >> 3, q = it & 7;
            int gr = rowBase + r;
            float4 v = make_float4(0.f, 0.f, 0.f, 0.f);
            if (gr < M) {
                v = *(const float4*)(A + (size_t)gr * K + k0 + q * 4);
                if (ACT) {
                    v.x = fmaxf(v.x + bias[k0 + q * 4 + 0], 0.0f);
                    v.y = fmaxf(v.y + bias[k0 + q * 4 + 1], 0.0f);
                    v.z = fmaxf(v.z + bias[k0 + q * 4 + 2], 0.0f);
                    v.w = fmaxf(v.w + bias[k0 + q * 4 + 3], 0.0f);
                }
            }
            aReg[i] = v;
        }
        #pragma unroll
        for (int i = 0; i < BI; i++) {
            int it = tid + i * 256;
            int n = it >> 2, j = it & 3;
            bRegH[i] = *(const uint4*)(Bt_hi + (size_t)n * K + k0 + j * 8);
            bRegL[i] = *(const uint4*)(Bt_lo + (size_t)n * K + k0 + j * 8);
        }
    };

    auto storeTile = [&]() {
        #pragma unroll
        for (int i = 0; i < 4; i++) {
            int it = tid + i * 256;
            int r = it >> 3, q = it & 7;
            float4 v = aReg[i];
            __nv_bfloat16 hx = __float2bfloat16(v.x);
            __nv_bfloat16 hy = __float2bfloat16(v.y);
            __nv_bfloat16 hz = __float2bfloat16(v.z);
            __nv_bfloat16 hw = __float2bfloat16(v.w);
            __nv_bfloat162 h01 = __nv_bfloat162(hx, hy);
            __nv_bfloat162 h23 = __nv_bfloat162(hz, hw);
            __nv_bfloat162 l01 = __nv_bfloat162(
                __float2bfloat16(v.x - __bfloat162float(hx)),
                __float2bfloat16(v.y - __bfloat162float(hy)));
            __nv_bfloat162 l23 = __nv_bfloat162(
                __float2bfloat16(v.z - __bfloat162float(hz)),
                __float2bfloat16(v.w - __bfloat162float(hw)));
            *(__nv_bfloat162*)&As_hi[r][q * 4]     = h01;
            *(__nv_bfloat162*)&As_hi[r][q * 4 + 2] = h23;
            *(__nv_bfloat162*)&As_lo[r][q * 4]     = l01;
            *(__nv_bfloat162*)&As_lo[r][q * 4 + 2] = l23;
        }
        #pragma unroll
        for (int i = 0; i < BI; i++) {
            int it = tid + i * 256;
            int n = it >> 2, j = it & 3;
            *(uint4*)&Bs_hi[n][j * 8] = bRegH[i];
            *(uint4*)&Bs_lo[n][j * 8] = bRegL[i];
        }
    };

    loadTile(0);

    for (int k0 = 0; k0 < K; k0 += 32) {
        storeTile();
        __syncthreads();
        if (k0 + 32 < K) loadTile(k0 + 32);

        #pragma unroll
        for (int ks = 0; ks < 2; ks++) {
            const int kk = ks * 16;
            uint32_t ah[2][4], al[2][4];
            #pragma unroll
            for (int mt = 0; mt < 2; mt++) {
                const __nv_bfloat16* ph = &As_hi[mBase + mt * 16 + g][kk + 2 * t];
                ah[mt][0] = *(const uint32_t*)ph;
                ah[mt][1] = *(const uint32_t*)(ph + 8 * SK);
                ah[mt][2] = *(const uint32_t*)(ph + 8);
                ah[mt][3] = *(const uint32_t*)(ph + 8 * SK + 8);
                const __nv_bfloat16* pl = &As_lo[mBase + mt * 16 + g][kk + 2 * t];
                al[mt][0] = *(const uint32_t*)pl;
                al[mt][1] = *(const uint32_t*)(pl + 8 * SK);
                al[mt][2] = *(const uint32_t*)(pl + 8);
                al[mt][3] = *(const uint32_t*)(pl + 8 * SK + 8);
            }
            #pragma unroll
            for (int nt = 0; nt < NT; nt++) {
                const __nv_bfloat16* pbh = &Bs_hi[nBase + nt * 8 + g][kk + 2 * t];
                uint32_t bh0 = *(const uint32_t*)pbh;
                uint32_t bh1 = *(const uint32_t*)(pbh + 8);
                const __nv_bfloat16* pbl = &Bs_lo[nBase + nt * 8 + g][kk + 2 * t];
                uint32_t bl0 = *(const uint32_t*)pbl;
                uint32_t bl1 = *(const uint32_t*)(pbl + 8);
                #pragma unroll
                for (int mt = 0; mt < 2; mt++) {
                    MMA_BF16(acc[mt][nt], ah[mt], bh0, bh1);
                    MMA_BF16(acc[mt][nt], ah[mt], bl0, bl1);
                    MMA_BF16(acc[mt][nt], al[mt], bh0, bh1);
                }
            }
        }
        __syncthreads();
    }

    // store C (fp32, row stride = BN == N)
    #pragma unroll
    for (int mt = 0; mt < 2; mt++) {
        int gr0 = rowBase + mBase + mt * 16 + g;
        #pragma unroll
        for (int nt = 0; nt < NT; nt++) {
            int col = nBase + nt * 8 + 2 * t;
            if (gr0 < M)
                *(float2*)(C + (size_t)gr0 * BN + col) =
                    make_float2(acc[mt][nt][0], acc[mt][nt][1]);
            if (gr0 + 8 < M)
                *(float2*)(C + (size_t)(gr0 + 8) * BN + col) =
                    make_float2(acc[mt][nt][2], acc[mt][nt][3]);
        }
    }
}

// ---------------- CSR aggregation (warp per node, selfloop fused) --------
__global__ void agg128_kernel(const float* __restrict__ h, float* __restrict__ out) {
    int n = blockIdx.x * 8 + (threadIdx.x >> 5);
    if (n >= NN) return;
    int lane = threadIdx.x & 31;

    float4 acc = *(const float4*)(h + (size_t)n * 128 + lane * 4);
    float w = g_invdeg[n];
    acc.x *= w; acc.y *= w; acc.z *= w; acc.w *= w;

    int beg = g_start[n];
    int end = beg + g_cnt[n];
    for (int j = beg; j < end; j++) {
        int s = g_csr_src[j];
        float c = g_csr_coef[j];
        float4 v = *(const float4*)(h + (size_t)s * 128 + lane * 4);
        acc.x = fmaf(c, v.x, acc.x);
        acc.y = fmaf(c, v.y, acc.y);
        acc.z = fmaf(c, v.z, acc.z);
        acc.w = fmaf(c, v.w, acc.w);
    }
    *(float4*)(out + (size_t)n * 128 + lane * 4) = acc;
}

__global__ void agg64_kernel(const float* __restrict__ h, float* __restrict__ out) {
    int n = blockIdx.x * 8 + (threadIdx.x >> 5);
    if (n >= NN) return;
    int lane = threadIdx.x & 31;

    float2 acc = *(const float2*)(h + (size_t)n * 64 + lane * 2);
    float w = g_invdeg[n];
    acc.x *= w; acc.y *= w;

    int beg = g_start[n];
    int end = beg + g_cnt[n];
    for (int j = beg; j < end; j++) {
        int s = g_csr_src[j];
        float c = g_csr_coef[j];
        float2 v = *(const float2*)(h + (size_t)s * 64 + lane * 2);
        acc.x = fmaf(c, v.x, acc.x);
        acc.y = fmaf(c, v.y, acc.y);
    }
    *(float2*)(out + (size_t)n * 64 + lane * 2) = acc;
}

// ---------------- pooling + head ----------------
__global__ void zero_pool_kernel() {
    int i = blockIdx.x * blockDim.x + threadIdx.x;
    if (i < NG * H3) g_gsum[i] = 0.0f;
    else if (i < NG * H3 + NG) g_gcnt[i - NG * H3] = 0.0f;
}

__global__ void pool_kernel(const float* __restrict__ agg3) {
    int idx = blockIdx.x * blockDim.x + threadIdx.x;
    if (idx >= NN * H3) return;
    int n = idx >> 6;
    int c = idx & 63;
    int g = g_batch[n];
    atomicAdd(&g_gsum[g * H3 + c], agg3[idx]);
    if (c == 0) atomicAdd(&g_gcnt[g], 1.0f);
}

__global__ void final_kernel(const float* __restrict__ Wlin,
                             const float* __restrict__ blin,
                             const float* __restrict__ b3,
                             float* __restrict__ out) {
    int g = threadIdx.x;
    if (g >= NG) return;
    float inv = 1.0f / fmaxf(g_gcnt[g], 1.0f);
    float a0 = blin[0], a1 = blin[1], a2 = blin[2];
    #pragma unroll 8
    for (int c = 0; c < H3; c++) {
        float p = g_gsum[g * H3 + c] * inv + b3[c];
        a0 += p * Wlin[c * 3 + 0];
        a1 += p * Wlin[c * 3 + 1];
        a2 += p * Wlin[c * 3 + 2];
    }
    out[g * 3 + 0] = a0;
    out[g * 3 + 1] = a1;
    out[g * 3 + 2] = a2;
}

// ---------------- launch ----------------
extern "C" void kernel_launch(void* const* d_in, const int* in_sizes, int n_in,
                              void* d_out, int out_size) {
    const float* x    = (const float*)d_in[0];
    const void*  ei   = d_in[1];
    const float* ew   = (const float*)d_in[2];
    const void*  bat  = d_in[3];
    const float* W1   = (const float*)d_in[4];
    const float* b1   = (const float*)d_in[5];
    const float* W2   = (const float*)d_in[6];
    const float* b2   = (const float*)d_in[7];
    const float* W3   = (const float*)d_in[8];
    const float* b3   = (const float*)d_in[9];
    const float* Wlin = (const float*)d_in[10];
    const float* blin = (const float*)d_in[11];
    float* out = (float*)d_out;

    float *bufA, *bufB;
    cudaGetSymbolAddress((void**)&bufA, g_bufA);
    cudaGetSymbolAddress((void**)&bufB, g_bufB);
    __nv_bfloat16 *w1h, *w1l, *w2h, *w2l, *w3h, *w3l;
    cudaGetSymbolAddress((void**)&w1h, g_w1t_hi);
    cudaGetSymbolAddress((void**)&w1l, g_w1t_lo);
    cudaGetSymbolAddress((void**)&w2h, g_w2t_hi);
    cudaGetSymbolAddress((void**)&w2l, g_w2t_lo);
    cudaGetSymbolAddress((void**)&w3h, g_w3t_hi);
    cudaGetSymbolAddress((void**)&w3l, g_w3t_lo);

    const int TPB = 256;
    const int gE = (NE + TPB - 1) / TPB;
    const int gN = (NN + TPB - 1) / TPB;
    const int nChunks = (NN + 255) / 256;

    // index dtype detection + conversion
    detect_kernel<<<1, 256>>>((const unsigned int*)ei);
    convert_edges_kernel<<<gE, TPB>>>(ei);
    convert_batch_kernel<<<gN, TPB>>>(bat);

    // degree + CSR build
    init_node_kernel<<<gN, TPB>>>();
    accum_deg_kernel<<<gE, TPB>>>(ew);
    dis_kernel<<<gN, TPB>>>();
    scan1_kernel<<<nChunks, 256>>>();
    scan2_kernel<<<1, 256>>>(nChunks);
    scan3_kernel<<<nChunks, 256>>>();
    fill_kernel<<<gE, TPB>>>(ew);

    // weight transpose + split (tiny)
    wsplit_kernel<<<(IN_DIM * H1 + 255) / 256, 256>>>(W1, w1h, w1l, IN_DIM, H1);
    wsplit_kernel<<<(H1 * H2 + 255) / 256, 256>>>(W2, w2h, w2l, H1, H2);
    wsplit_kernel<<<(H2 * H3 + 255) / 256, 256>>>(W3, w3h, w3l, H2, H3);

    const int MB = (NN + 127) / 128;  // 391
    dim3 gGemm(1, MB);
    const int gAgg = (NN + 7) / 8;

    // ---- layer 1 ----
    hgemm_kernel<128, 0><<<gGemm, 256>>>(NN, IN_DIM, x, w1h, w1l, bufA, nullptr);
    agg128_kernel<<<gAgg, 256>>>(bufA, bufB);

    // ---- layer 2 ----
    hgemm_kernel<128, 1><<<gGemm, 256>>>(NN, H1, bufB, w2h, w2l, bufA, b1);
    agg128_kernel<<<gAgg, 256>>>(bufA, bufB);

    // ---- layer 3 ----
    hgemm_kernel<64, 1><<<gGemm, 256>>>(NN, H2, bufB, w3h, w3l, bufA, b2);
    agg64_kernel<<<gAgg, 256>>>(bufA, bufB);

    // ---- pool + head ----
    zero_pool_kernel<<<(NG * H3 + NG + TPB - 1) / TPB, TPB>>>();
    pool_kernel<<<(NN * H3 + TPB - 1) / TPB, TPB>>>(bufB);
    final_kernel<<<1, 64>>>(Wlin, blin, b3, out);
}